// round 16
// baseline (speedup 1.0000x reference)
#include <cuda_runtime.h>
#include <cuda_bf16.h>
#include <stdint.h>

#define D   1024
#define DD  (D*D)
#define BSZ 16384
typedef __nv_bfloat16 bf16;
typedef unsigned int u32;

// ---------------- scratch (device globals) -----------------------------------
__device__ float gWf[3*DD], gYf[3*DD], gPf[3*DD];
// 3-way (h,m,l) packs
__device__ bf16 gWT[3][3*DD], gWp[3][3*DD], gXT[3][3*DD];
__device__ bf16 gXa[3][3*DD], gXb[3][3*DD];
__device__ bf16 gYp[3][3*DD], gYT[3][3*DD], gZT[3][3*DD];
__device__ bf16 gQa[3][3*DD], gQb[3][3*DD], gQTa[3][3*DD], gQTb[3][3*DD];
__device__ bf16 gMp[3][3*DD];
// 2-way terminal packs
__device__ bf16 gKT[2][3*DD];
__device__ bf16 gx[2][(size_t)BSZ*D];
__device__ bf16 gA1[2][(size_t)BSZ*D];
__device__ bf16 gA2[2][(size_t)BSZ*D];

__device__ __forceinline__ void split3(float v, unsigned short& h,
                                       unsigned short& m, unsigned short& l) {
    bf16 hb = __float2bfloat16(v);
    float r = v - __bfloat162float(hb);
    bf16 mb = __float2bfloat16(r);
    float r2 = r - __bfloat162float(mb);
    h = __bfloat16_as_ushort(hb);
    m = __bfloat16_as_ushort(mb);
    l = __bfloat16_as_ushort(__float2bfloat16(r2));
}
__device__ __forceinline__ void split2(float v, unsigned short& h, unsigned short& l) {
    bf16 hb = __float2bfloat16(v);
    h = __bfloat16_as_ushort(hb);
    l = __bfloat16_as_ushort(__float2bfloat16(v - __bfloat162float(hb)));
}

// pipeline smem: 4 stages x (A 64x40 + B 128x40) bf16 = 61440 B
#define SPITCH 40
#define STAGEA (64 * SPITCH)
#define STAGEB (128 * SPITCH)
#define STAGEE (STAGEA + STAGEB)
#define SMEMSZ (4 * STAGEE * 2)            // 61440 bytes
#define TPITCH 68                           // fp32 transpose staging pitch

// ---------------- HMMA multi-pass split GEMM -----------------------------------
// C[m][n] = epi( sum_k A[m][k]*B_data[n][k] )  (C = A * B_data^T)
// NP=6: exact 3-way split (fp32-grade) passes hh,hm,mh,hl,mm,lh.
// NP=3: cheap passes hh,hm,mh on the same 3-way packs (2-way quality).
// EPI 0: c1*acc + cd*I   1: c1*acc + c2*aux1 + cd*I
//     2: 0.5*aux1 + 0.45*aux2 - 0.5*acc   3: acc+bias   4: lipswish(acc+bias)
// WF: write fp32 Cf. NW: 0/2/3 normal packs C0..  TW: 0/2/3 transposed packs T0..
// 256 threads, 8 warps (2 x 4), warp 32x32, CTA 64x128, 4-stage cp.async pipe,
// 3 CTAs/SM residency.
template<int EPI, int WF, int NW, int TW, int NP>
__global__ void __launch_bounds__(256, 3)
gemm(const bf16* __restrict__ A0, const bf16* __restrict__ A1, const bf16* __restrict__ A2,
     const bf16* __restrict__ B0, const bf16* __restrict__ B1, const bf16* __restrict__ B2,
     float* __restrict__ Cf,
     bf16* __restrict__ C0, bf16* __restrict__ C1, bf16* __restrict__ C2,
     bf16* __restrict__ T0, bf16* __restrict__ T1, bf16* __restrict__ T2,
     const float* __restrict__ aux1, const float* __restrict__ aux2,
     const float* __restrict__ bias,
     float cd, float c1, float c2, int M)
{
    extern __shared__ __align__(16) char smem[];
    bf16* sbuf = (bf16*)smem;

    const int tid  = threadIdx.x;
    const int w    = tid >> 5, lane = tid & 31;
    const int wm   = w >> 2,  wn   = w & 3;        // 2 x 4 warps
    const int m0   = blockIdx.y * 64, n0 = blockIdx.x * 128;
    const size_t ab = (size_t)blockIdx.z * (size_t)M * D;
    const size_t bb = (size_t)blockIdx.z * (size_t)DD;

    const bf16* Al[3] = {A0, A1, A2};
    const bf16* Bl[3] = {B0, B1, B2};
    const int pAi6[6] = {0,0,1,0,1,2}, pBi6[6] = {0,1,0,2,1,0};
    const int pAi3[3] = {0,0,1},       pBi3[3] = {0,1,0};

    float c[2][4][4];
#pragma unroll
    for (int i = 0; i < 2; i++)
#pragma unroll
        for (int j = 0; j < 4; j++)
#pragma unroll
            for (int k = 0; k < 4; k++) c[i][j][k] = 0.0f;

    auto load = [&](int kt) {
        const int stg  = kt & 3;
        const int pass = kt >> 5;
        const int k0   = (kt & 31) << 5;
        const bf16* pA = Al[NP == 6 ? pAi6[pass] : pAi3[pass]] + ab;
        const bf16* pB = Bl[NP == 6 ? pBi6[pass] : pBi3[pass]] + bb;
        bf16* dA0 = sbuf + stg * STAGEE;
        bf16* dB0 = dA0 + STAGEA;
        {   // A: 64 rows x 32 k
            int r = tid >> 2, cb = tid & 3;
            u32 dA = (u32)__cvta_generic_to_shared(dA0 + r * SPITCH + cb * 8);
            asm volatile("cp.async.cg.shared.global [%0], [%1], 16;"
                         :: "r"(dA), "l"(pA + (size_t)(m0 + r) * D + k0 + cb * 8));
        }
#pragma unroll
        for (int i = 0; i < 2; i++) {   // B: 128 rows
            int id = i * 256 + tid;
            int r = id >> 2, cb = id & 3;
            u32 dB = (u32)__cvta_generic_to_shared(dB0 + r * SPITCH + cb * 8);
            asm volatile("cp.async.cg.shared.global [%0], [%1], 16;"
                         :: "r"(dB), "l"(pB + (size_t)(n0 + r) * D + k0 + cb * 8));
        }
        asm volatile("cp.async.commit_group;");
    };

    // hoisted ldmatrix byte offsets (within a stage)
    const int lmRow = lane & 15;
    const int lmCol = (lane >> 4) * 8;
    const u32 sbase = (u32)__cvta_generic_to_shared(sbuf);
    u32 offA[2], offB[2];
#pragma unroll
    for (int mi = 0; mi < 2; mi++)
        offA[mi] = ((wm * 32 + mi * 16 + lmRow) * SPITCH + lmCol) * 2;
#pragma unroll
    for (int nb = 0; nb < 2; nb++)
        offB[nb] = ((wn * 32 + nb * 16 + lmRow) * SPITCH + lmCol) * 2 + STAGEA * 2;

    const int NT = NP * 32;
    load(0); load(1); load(2);
    for (int kt = 0; kt < NT; kt++) {
        const int rem = NT - 1 - kt;
        if (rem >= 2)      asm volatile("cp.async.wait_group 2;");
        else if (rem == 1) asm volatile("cp.async.wait_group 1;");
        else               asm volatile("cp.async.wait_group 0;");
        __syncthreads();
        if (kt + 3 < NT) load(kt + 3);

        const u32 stgb = sbase + (u32)(kt & 3) * (STAGEE * 2);
#pragma unroll
        for (int ks = 0; ks < 2; ks++) {
            const u32 ko = ks * 32;           // 16 bf16 = 32 bytes
            u32 a[2][4], b[4][2];
#pragma unroll
            for (int mi = 0; mi < 2; mi++)
                asm volatile("ldmatrix.sync.aligned.m8n8.x4.shared.b16 {%0,%1,%2,%3}, [%4];"
                    : "=r"(a[mi][0]), "=r"(a[mi][1]), "=r"(a[mi][2]), "=r"(a[mi][3])
                    : "r"(stgb + offA[mi] + ko));
#pragma unroll
            for (int nb = 0; nb < 2; nb++) {
                u32 b0, b1, b2, b3;
                asm volatile("ldmatrix.sync.aligned.m8n8.x4.shared.b16 {%0,%1,%2,%3}, [%4];"
                    : "=r"(b0), "=r"(b1), "=r"(b2), "=r"(b3)
                    : "r"(stgb + offB[nb] + ko));
                b[2 * nb][0]     = b0; b[2 * nb][1]     = b2;
                b[2 * nb + 1][0] = b1; b[2 * nb + 1][1] = b3;
            }
#pragma unroll
            for (int mi = 0; mi < 2; mi++)
#pragma unroll
                for (int ni = 0; ni < 4; ni++)
                    asm volatile(
                        "mma.sync.aligned.m16n8k16.row.col.f32.bf16.bf16.f32 "
                        "{%0,%1,%2,%3}, {%4,%5,%6,%7}, {%8,%9}, {%0,%1,%2,%3};"
                        : "+f"(c[mi][ni][0]), "+f"(c[mi][ni][1]),
                          "+f"(c[mi][ni][2]), "+f"(c[mi][ni][3])
                        : "r"(a[mi][0]), "r"(a[mi][1]), "r"(a[mi][2]), "r"(a[mi][3]),
                          "r"(b[ni][0]), "r"(b[ni][1]));
        }
    }

    // ---------------- fused epilogue ------------------------------------------
    const int lr = lane >> 2, lc = (lane & 3) * 2;
    const int r0 = m0 + wm * 32, cb0 = n0 + wn * 32;
#pragma unroll
    for (int mi = 0; mi < 2; mi++)
#pragma unroll
        for (int ni = 0; ni < 4; ni++)
#pragma unroll
            for (int h = 0; h < 2; h++) {
                const int row = r0 + mi * 16 + lr + h * 8;
                const int col = cb0 + ni * 8 + lc;
                float v0 = c[mi][ni][h * 2], v1 = c[mi][ni][h * 2 + 1];
                const size_t off = ab + (size_t)row * D + col;
                if (EPI == 0) {
                    v0 = c1 * v0; v1 = c1 * v1;
                    if (row == col)     v0 += cd;
                    if (row == col + 1) v1 += cd;
                } else if (EPI == 1) {
                    float2 a1 = *(const float2*)(aux1 + off);
                    v0 = c1 * v0 + c2 * a1.x; v1 = c1 * v1 + c2 * a1.y;
                    if (row == col)     v0 += cd;
                    if (row == col + 1) v1 += cd;
                } else if (EPI == 2) {
                    float2 a1 = *(const float2*)(aux1 + off);
                    float2 a2 = *(const float2*)(aux2 + off);
                    v0 = 0.5f * a1.x + 0.45f * a2.x - 0.5f * v0;
                    v1 = 0.5f * a1.y + 0.45f * a2.y - 0.5f * v1;
                } else if (EPI == 3) {
                    v0 += __ldg(bias + col); v1 += __ldg(bias + col + 1);
                } else { // lipswish
                    v0 += __ldg(bias + col); v1 += __ldg(bias + col + 1);
                    v0 = __fdividef(v0 * (1.0f / 1.1f), 1.0f + __expf(-v0));
                    v1 = __fdividef(v1 * (1.0f / 1.1f), 1.0f + __expf(-v1));
                }
                if (WF) {
                    float2 o; o.x = v0; o.y = v1;
                    *(float2*)(Cf + off) = o;
                }
                if (NW == 2) {
                    unsigned short h0, l0, h1, l1;
                    split2(v0, h0, l0); split2(v1, h1, l1);
                    *(u32*)(C0 + off) = (u32)h0 | ((u32)h1 << 16);
                    *(u32*)(C1 + off) = (u32)l0 | ((u32)l1 << 16);
                } else if (NW == 3) {
                    unsigned short h0, m0s, l0, h1, m1s, l1;
                    split3(v0, h0, m0s, l0); split3(v1, h1, m1s, l1);
                    *(u32*)(C0 + off) = (u32)h0  | ((u32)h1  << 16);
                    *(u32*)(C1 + off) = (u32)m0s | ((u32)m1s << 16);
                    *(u32*)(C2 + off) = (u32)l0  | ((u32)l1  << 16);
                }
                c[mi][ni][h * 2] = v0; c[mi][ni][h * 2 + 1] = v1;
            }

    if (TW) {
        // stage the tile transposed in smem (fp32): ts[col(128)][row(64)]
        float* ts = (float*)smem;
        __syncthreads();
#pragma unroll
        for (int mi = 0; mi < 2; mi++)
#pragma unroll
            for (int ni = 0; ni < 4; ni++)
#pragma unroll
                for (int h = 0; h < 2; h++) {
                    const int rl = wm * 32 + mi * 16 + lr + h * 8;
                    const int cl = wn * 32 + ni * 8 + lc;
                    ts[(cl    ) * TPITCH + rl] = c[mi][ni][h * 2];
                    ts[(cl + 1) * TPITCH + rl] = c[mi][ni][h * 2 + 1];
                }
        __syncthreads();
#pragma unroll
        for (int i = 0; i < 16; i++) {
            const int tr = w * 16 + i;               // output T-row (= col index)
            float2 vv = *(const float2*)&ts[tr * TPITCH + lane * 2];
            const size_t toff = bb + (size_t)(n0 + tr) * D + m0 + lane * 2;
            if (TW == 3) {
                unsigned short h0,m0s,l0, h1,m1s,l1;
                split3(vv.x, h0, m0s, l0); split3(vv.y, h1, m1s, l1);
                *(u32*)(T0 + toff) = (u32)h0  | ((u32)h1  << 16);
                *(u32*)(T1 + toff) = (u32)m0s | ((u32)m1s << 16);
                *(u32*)(T2 + toff) = (u32)l0  | ((u32)l1  << 16);
            } else {
                unsigned short h0,l0, h1,l1;
                split2(vv.x, h0, l0); split2(vv.y, h1, l1);
                *(u32*)(T0 + toff) = (u32)h0 | ((u32)h1 << 16);
                *(u32*)(T1 + toff) = (u32)l0 | ((u32)l1 << 16);
            }
        }
    }
}

// ---------------- pack kernels -------------------------------------------------
__global__ void packS3(const float* __restrict__ in, bf16* __restrict__ o0,
                       bf16* __restrict__ o1, bf16* __restrict__ o2, int n4)
{
    int i = blockIdx.x * 256 + threadIdx.x;
    if (i >= n4) return;
    float4 v = ((const float4*)in)[i];
    ushort4 H, Mv, L;
    split3(v.x, H.x, Mv.x, L.x); split3(v.y, H.y, Mv.y, L.y);
    split3(v.z, H.z, Mv.z, L.z); split3(v.w, H.w, Mv.w, L.w);
    ((ushort4*)o0)[i] = H; ((ushort4*)o1)[i] = Mv; ((ushort4*)o2)[i] = L;
}

__global__ void packS2(const float* __restrict__ in, bf16* __restrict__ o0,
                       bf16* __restrict__ o1, int n4)
{
    int i = blockIdx.x * 256 + threadIdx.x;
    if (i >= n4) return;
    float4 v = ((const float4*)in)[i];
    ushort4 H, L;
    split2(v.x, H.x, L.x); split2(v.y, H.y, L.y);
    split2(v.z, H.z, L.z); split2(v.w, H.w, L.w);
    ((ushort4*)o0)[i] = H; ((ushort4*)o1)[i] = L;
}

__global__ void packC3(const float* __restrict__ w, const float* __restrict__ p,
                       bf16* __restrict__ o0, bf16* __restrict__ o1,
                       bf16* __restrict__ o2, int n4)
{
    int i = blockIdx.x * 256 + threadIdx.x;
    if (i >= n4) return;
    float4 a = ((const float4*)w)[i];
    float4 b = ((const float4*)p)[i];
    float4 v;
    v.x = a.x - 0.9f * b.x; v.y = a.y - 0.9f * b.y;
    v.z = a.z - 0.9f * b.z; v.w = a.w - 0.9f * b.w;
    ushort4 H, Mv, L;
    split3(v.x, H.x, Mv.x, L.x); split3(v.y, H.y, Mv.y, L.y);
    split3(v.z, H.z, Mv.z, L.z); split3(v.w, H.w, Mv.w, L.w);
    ((ushort4*)o0)[i] = H; ((ushort4*)o1)[i] = Mv; ((ushort4*)o2)[i] = L;
}

// transposed 3-way pack (used ONCE, for W)
__global__ void packT3(const float* __restrict__ in, bf16* __restrict__ o0,
                       bf16* __restrict__ o1, bf16* __restrict__ o2)
{
    __shared__ float t[32][33];
    const int b = blockIdx.z;
    in += (size_t)b * DD; o0 += (size_t)b * DD; o1 += (size_t)b * DD; o2 += (size_t)b * DD;
    const int bx = blockIdx.x * 32, by = blockIdx.y * 32;
    const int x = threadIdx.x, y = threadIdx.y;
#pragma unroll
    for (int i = 0; i < 4; i++)
        t[y + i * 8][x] = in[(size_t)(by + y + i * 8) * D + bx + x];
    __syncthreads();
#pragma unroll
    for (int i = 0; i < 4; i++) {
        float v = t[x][y + i * 8];
        unsigned short h, m, l;
        split3(v, h, m, l);
        size_t o = (size_t)(bx + y + i * 8) * D + by + x;
        o0[o] = __ushort_as_bfloat16(h);
        o1[o] = __ushort_as_bfloat16(m);
        o2[o] = __ushort_as_bfloat16(l);
    }
}

// ---------------- launcher ------------------------------------------------------
extern "C" void kernel_launch(void* const* d_in, const int* in_sizes, int n_in,
                              void* d_out, int out_size)
{
    const float* x       = (const float*)d_in[0];
    const float* w[3]    = {(const float*)d_in[1], (const float*)d_in[3], (const float*)d_in[5]};
    const float* bias[3] = {(const float*)d_in[2], (const float*)d_in[4], (const float*)d_in[6]};

    float *Wf, *Yf, *Pf;
    cudaGetSymbolAddress((void**)&Wf, gWf);
    cudaGetSymbolAddress((void**)&Yf, gYf);
    cudaGetSymbolAddress((void**)&Pf, gPf);

    bf16 *WT[3], *Wp[3], *XT[3], *Xa[3], *Xb[3];
    bf16 *Yp[3], *YT[3], *ZT[3];
    bf16 *Qa[3], *Qb[3], *QTa[3], *QTb[3], *Mp[3];
    bf16 *KT[2], *xp[2], *A1[2], *A2[2];
    for (int i = 0; i < 3; i++) {
        cudaGetSymbolAddress((void**)&WT[i],  gWT);  WT[i]  += (size_t)i * 3 * DD;
        cudaGetSymbolAddress((void**)&Wp[i],  gWp);  Wp[i]  += (size_t)i * 3 * DD;
        cudaGetSymbolAddress((void**)&XT[i],  gXT);  XT[i]  += (size_t)i * 3 * DD;
        cudaGetSymbolAddress((void**)&Xa[i],  gXa);  Xa[i]  += (size_t)i * 3 * DD;
        cudaGetSymbolAddress((void**)&Xb[i],  gXb);  Xb[i]  += (size_t)i * 3 * DD;
        cudaGetSymbolAddress((void**)&Yp[i],  gYp);  Yp[i]  += (size_t)i * 3 * DD;
        cudaGetSymbolAddress((void**)&YT[i],  gYT);  YT[i]  += (size_t)i * 3 * DD;
        cudaGetSymbolAddress((void**)&ZT[i],  gZT);  ZT[i]  += (size_t)i * 3 * DD;
        cudaGetSymbolAddress((void**)&Qa[i],  gQa);  Qa[i]  += (size_t)i * 3 * DD;
        cudaGetSymbolAddress((void**)&Qb[i],  gQb);  Qb[i]  += (size_t)i * 3 * DD;
        cudaGetSymbolAddress((void**)&QTa[i], gQTa); QTa[i] += (size_t)i * 3 * DD;
        cudaGetSymbolAddress((void**)&QTb[i], gQTb); QTb[i] += (size_t)i * 3 * DD;
        cudaGetSymbolAddress((void**)&Mp[i],  gMp);  Mp[i]  += (size_t)i * 3 * DD;
    }
    for (int i = 0; i < 2; i++) {
        cudaGetSymbolAddress((void**)&KT[i], gKT); KT[i] += (size_t)i * 3 * DD;
        cudaGetSymbolAddress((void**)&xp[i], gx);  xp[i] += (size_t)i * BSZ * D;
        cudaGetSymbolAddress((void**)&A1[i], gA1); A1[i] += (size_t)i * BSZ * D;
        cudaGetSymbolAddress((void**)&A2[i], gA2); A2[i] += (size_t)i * BSZ * D;
    }

    cudaFuncSetAttribute(gemm<0,1,3,3,3>, cudaFuncAttributeMaxDynamicSharedMemorySize, SMEMSZ);
    cudaFuncSetAttribute(gemm<1,0,0,3,3>, cudaFuncAttributeMaxDynamicSharedMemorySize, SMEMSZ);
    cudaFuncSetAttribute(gemm<0,0,3,3,3>, cudaFuncAttributeMaxDynamicSharedMemorySize, SMEMSZ);
    cudaFuncSetAttribute(gemm<0,0,0,3,3>, cudaFuncAttributeMaxDynamicSharedMemorySize, SMEMSZ);
    cudaFuncSetAttribute(gemm<0,0,0,3,6>, cudaFuncAttributeMaxDynamicSharedMemorySize, SMEMSZ);
    cudaFuncSetAttribute(gemm<0,1,3,3,6>, cudaFuncAttributeMaxDynamicSharedMemorySize, SMEMSZ);
    cudaFuncSetAttribute(gemm<0,0,3,3,6>, cudaFuncAttributeMaxDynamicSharedMemorySize, SMEMSZ);
    cudaFuncSetAttribute(gemm<2,0,0,2,3>, cudaFuncAttributeMaxDynamicSharedMemorySize, SMEMSZ);
    cudaFuncSetAttribute(gemm<4,0,2,0,3>, cudaFuncAttributeMaxDynamicSharedMemorySize, SMEMSZ);
    cudaFuncSetAttribute(gemm<3,1,0,0,3>, cudaFuncAttributeMaxDynamicSharedMemorySize, SMEMSZ);

    for (int i = 0; i < 3; i++)
        cudaMemcpyAsync(Wf + (size_t)i * DD, w[i], (size_t)DD * sizeof(float),
                        cudaMemcpyDeviceToDevice);

    const dim3 gw(8, 16, 3), gx_(8, 256, 1), bk(256);
    const dim3 gt(32, 32, 3), bt(32, 8);
    const float q5a = 3.4445f, q5b = -4.7750f, q5c = 2.0315f;
    const float s0 = 1.0f / 2.2f;
    const float* NF = nullptr;
    bf16* NB = nullptr;

    packS2<<<16384, 256>>>(x, xp[0], xp[1], BSZ * D / 4);
    packS3<<<3072, 256>>>(Wf, Wp[0], Wp[1], Wp[2], 3 * DD / 4);
    packT3<<<gt, bt>>>(Wf, WT[0], WT[1], WT[2]);

    // ---- P = msign(W): 4 cheap quintics + 3 cheap NS + 1 full NS ----
    gemm<0,1,3,3,3><<<gw,bk,SMEMSZ>>>(WT[0],WT[1],WT[2], WT[0],WT[1],WT[2], Yf,
        Yp[0],Yp[1],Yp[2], YT[0],YT[1],YT[2], NF,NF,NF, 0.f, s0*s0, 0.f, D);
    gemm<1,0,0,3,3><<<gw,bk,SMEMSZ>>>(Yp[0],Yp[1],Yp[2], YT[0],YT[1],YT[2], nullptr,
        NB,NB,NB, ZT[0],ZT[1],ZT[2], Yf,NF,NF, q5a, q5c, q5b, D);
    gemm<0,0,3,3,3><<<gw,bk,SMEMSZ>>>(Wp[0],Wp[1],Wp[2], ZT[0],ZT[1],ZT[2], nullptr,
        Xa[0],Xa[1],Xa[2], XT[0],XT[1],XT[2], NF,NF,NF, 0.f, s0, 0.f, D);

    bf16 **cur = Xa, **nxt = Xb;
    for (int it = 0; it < 3; it++) {   // 3 more cheap quintics (4 total)
        gemm<0,1,3,3,3><<<gw,bk,SMEMSZ>>>(XT[0],XT[1],XT[2], XT[0],XT[1],XT[2], Yf,
            Yp[0],Yp[1],Yp[2], YT[0],YT[1],YT[2], NF,NF,NF, 0.f, 1.f, 0.f, D);
        gemm<1,0,0,3,3><<<gw,bk,SMEMSZ>>>(Yp[0],Yp[1],Yp[2], YT[0],YT[1],YT[2], nullptr,
            NB,NB,NB, ZT[0],ZT[1],ZT[2], Yf,NF,NF, q5a, q5c, q5b, D);
        gemm<0,0,3,3,3><<<gw,bk,SMEMSZ>>>(cur[0],cur[1],cur[2], ZT[0],ZT[1],ZT[2], nullptr,
            nxt[0],nxt[1],nxt[2], XT[0],XT[1],XT[2], NF,NF,NF, 0.f, 1.f, 0.f, D);
        bf16** t = cur; cur = nxt; nxt = t;
    }
    for (int it = 0; it < 3; it++) {   // 3 cheap NS
        gemm<0,0,0,3,3><<<gw,bk,SMEMSZ>>>(XT[0],XT[1],XT[2], XT[0],XT[1],XT[2], nullptr,
            NB,NB,NB, ZT[0],ZT[1],ZT[2], NF,NF,NF, 1.5f, -0.5f, 0.f, D);
        gemm<0,0,3,3,3><<<gw,bk,SMEMSZ>>>(cur[0],cur[1],cur[2], ZT[0],ZT[1],ZT[2], nullptr,
            nxt[0],nxt[1],nxt[2], XT[0],XT[1],XT[2], NF,NF,NF, 0.f, 1.f, 0.f, D);
        bf16** t = cur; cur = nxt; nxt = t;
    }
    {   // final NS — FULL precision (sets terminal accuracy of P)
        gemm<0,0,0,3,6><<<gw,bk,SMEMSZ>>>(XT[0],XT[1],XT[2], XT[0],XT[1],XT[2], nullptr,
            NB,NB,NB, ZT[0],ZT[1],ZT[2], NF,NF,NF, 1.5f, -0.5f, 0.f, D);
        gemm<0,1,3,3,6><<<gw,bk,SMEMSZ>>>(cur[0],cur[1],cur[2], ZT[0],ZT[1],ZT[2], Pf,
            nxt[0],nxt[1],nxt[2], XT[0],XT[1],XT[2], NF,NF,NF, 0.f, 1.f, 0.f, D);
        bf16** t = cur; cur = nxt; nxt = t;
    }
    // Pf = P (fp32); XT = packT(P)

    // ---- Q = sign((P^T W - 0.9I)/1.15): 5 cheap quintics + 3 cheap NS + 1 full NS ----
    bf16 **q = Qa, **qT = QTa, **r = Qb, **rT = QTb;
    gemm<0,0,3,3,3><<<gw,bk,SMEMSZ>>>(XT[0],XT[1],XT[2], WT[0],WT[1],WT[2], nullptr,
        q[0],q[1],q[2], qT[0],qT[1],qT[2], NF,NF,NF, -0.9f/1.15f, 1.f/1.15f, 0.f, D);
    for (int it = 0; it < 5; it++) {   // cheap quintics
        gemm<0,1,3,3,3><<<gw,bk,SMEMSZ>>>(q[0],q[1],q[2], qT[0],qT[1],qT[2], Yf,
            Yp[0],Yp[1],Yp[2], YT[0],YT[1],YT[2], NF,NF,NF, 0.f, 1.f, 0.f, D);
        gemm<1,0,0,3,3><<<gw,bk,SMEMSZ>>>(Yp[0],Yp[1],Yp[2], YT[0],YT[1],YT[2], nullptr,
            NB,NB,NB, ZT[0],ZT[1],ZT[2], Yf,NF,NF, q5a, q5c, q5b, D);
        gemm<0,0,3,3,3><<<gw,bk,SMEMSZ>>>(q[0],q[1],q[2], ZT[0],ZT[1],ZT[2], nullptr,
            r[0],r[1],r[2], rT[0],rT[1],rT[2], NF,NF,NF, 0.f, 1.f, 0.f, D);
        bf16** t = q; q = r; r = t;
        t = qT; qT = rT; rT = t;
    }
    for (int it = 0; it < 3; it++) {   // cheap NS
        gemm<0,0,0,3,3><<<gw,bk,SMEMSZ>>>(q[0],q[1],q[2], qT[0],qT[1],qT[2], nullptr,
            NB,NB,NB, ZT[0],ZT[1],ZT[2], NF,NF,NF, 1.5f, -0.5f, 0.f, D);
        gemm<0,0,3,3,3><<<gw,bk,SMEMSZ>>>(q[0],q[1],q[2], ZT[0],ZT[1],ZT[2], nullptr,
            r[0],r[1],r[2], rT[0],rT[1],rT[2], NF,NF,NF, 0.f, 1.f, 0.f, D);
        bf16** t = q; q = r; r = t;
        t = qT; qT = rT; rT = t;
    }
    {   // final NS — FULL precision (sets terminal accuracy of Q)
        gemm<0,0,0,3,6><<<gw,bk,SMEMSZ>>>(q[0],q[1],q[2], qT[0],qT[1],qT[2], nullptr,
            NB,NB,NB, ZT[0],ZT[1],ZT[2], NF,NF,NF, 1.5f, -0.5f, 0.f, D);
        gemm<0,0,3,3,6><<<gw,bk,SMEMSZ>>>(q[0],q[1],q[2], ZT[0],ZT[1],ZT[2], nullptr,
            r[0],r[1],r[2], rT[0],rT[1],rT[2], NF,NF,NF, 0.f, 1.f, 0.f, D);
        bf16** t = q; q = r; r = t;
        t = qT; qT = rT; rT = t;
    }

    // ---- K = 0.5(W + 0.9P - (W-0.9P)Q): KT produced directly (2-way, transposed) ----
    packC3<<<3072, 256>>>(Wf, Pf, Mp[0], Mp[1], Mp[2], 3 * DD / 4);
    gemm<2,0,0,2,3><<<gw,bk,SMEMSZ>>>(Mp[0],Mp[1],Mp[2], qT[0],qT[1],qT[2], nullptr,
        NB,NB,NB, KT[0],KT[1],NB, Wf, Pf, NF, 0.f, 0.f, 0.f, D);

    // ---- activation chain (3-pass 2-way; terminal) ----
    gemm<4,0,2,0,3><<<gx_,bk,SMEMSZ>>>(xp[0],xp[1],NB, KT[0],KT[1],NB, nullptr,
        A1[0],A1[1],NB, NB,NB,NB, NF,NF, bias[0], 0.f,0.f,0.f, BSZ);
    gemm<4,0,2,0,3><<<gx_,bk,SMEMSZ>>>(A1[0],A1[1],NB, KT[0]+DD,KT[1]+DD,NB, nullptr,
        A2[0],A2[1],NB, NB,NB,NB, NF,NF, bias[1], 0.f,0.f,0.f, BSZ);
    gemm<3,1,0,0,3><<<gx_,bk,SMEMSZ>>>(A2[0],A2[1],NB, KT[0]+2*DD,KT[1]+2*DD,NB, (float*)d_out,
        NB,NB,NB, NB,NB,NB, NF,NF, bias[2], 0.f,0.f,0.f, BSZ);
}

// round 17
// speedup vs baseline: 1.7306x; 1.7306x over previous
#include <cuda_runtime.h>
#include <cuda_bf16.h>
#include <stdint.h>

#define D   1024
#define DD  (D*D)
#define BSZ 16384
typedef __nv_bfloat16 bf16;
typedef unsigned int u32;

// ---------------- scratch (device globals) -----------------------------------
__device__ float gWf[3*DD], gYf[3*DD], gPf[3*DD];
// 3-way (h,m,l) packs
__device__ bf16 gWT[3][3*DD], gWp[3][3*DD], gXT[3][3*DD];
__device__ bf16 gXa[3][3*DD], gXb[3][3*DD];
__device__ bf16 gYp[3][3*DD], gYT[3][3*DD], gZT[3][3*DD];
__device__ bf16 gQa[3][3*DD], gQb[3][3*DD], gQTa[3][3*DD], gQTb[3][3*DD];
__device__ bf16 gMp[3][3*DD];
// 2-way terminal packs
__device__ bf16 gKT[2][3*DD];
__device__ bf16 gx[2][(size_t)BSZ*D];
__device__ bf16 gA1[2][(size_t)BSZ*D];
__device__ bf16 gA2[2][(size_t)BSZ*D];

__device__ __forceinline__ void split3(float v, unsigned short& h,
                                       unsigned short& m, unsigned short& l) {
    bf16 hb = __float2bfloat16(v);
    float r = v - __bfloat162float(hb);
    bf16 mb = __float2bfloat16(r);
    float r2 = r - __bfloat162float(mb);
    h = __bfloat16_as_ushort(hb);
    m = __bfloat16_as_ushort(mb);
    l = __bfloat16_as_ushort(__float2bfloat16(r2));
}
__device__ __forceinline__ void split2(float v, unsigned short& h, unsigned short& l) {
    bf16 hb = __float2bfloat16(v);
    h = __bfloat16_as_ushort(hb);
    l = __bfloat16_as_ushort(__float2bfloat16(v - __bfloat162float(hb)));
}

// pipeline smem: 4 stages x (A 64x40 + B 128x40) bf16 = 61440 B
#define SPITCH 40
#define STAGEA (64 * SPITCH)
#define STAGEB (128 * SPITCH)
#define STAGEE (STAGEA + STAGEB)
#define SMEMSZ (4 * STAGEE * 2)            // 61440 bytes
#define TPITCH 68                           // fp32 transpose staging pitch

// ---------------- HMMA multi-pass split GEMM -----------------------------------
// C[m][n] = epi( sum_k A[m][k]*B_data[n][k] )  (C = A * B_data^T)
// NP=6: exact 3-way split (fp32-grade) passes hh,hm,mh,hl,mm,lh.
// NP=3: cheap passes hh,hm,mh on the same 3-way packs (2-way quality).
// EPI 0: c1*acc + cd*I   1: c1*acc + c2*aux1 + cd*I
//     2: 0.5*aux1 + 0.45*aux2 - 0.5*acc   3: acc+bias   4: lipswish(acc+bias)
// WF: write fp32 Cf. NW: 0/2/3 normal packs C0..  TW: 0/2/3 transposed packs T0..
// 256 threads, 8 warps (2 x 4), warp 32x32, CTA 64x128, 4-stage cp.async pipe,
// 3 CTAs/SM residency.
template<int EPI, int WF, int NW, int TW, int NP>
__global__ void __launch_bounds__(256, 3)
gemm(const bf16* __restrict__ A0, const bf16* __restrict__ A1, const bf16* __restrict__ A2,
     const bf16* __restrict__ B0, const bf16* __restrict__ B1, const bf16* __restrict__ B2,
     float* __restrict__ Cf,
     bf16* __restrict__ C0, bf16* __restrict__ C1, bf16* __restrict__ C2,
     bf16* __restrict__ T0, bf16* __restrict__ T1, bf16* __restrict__ T2,
     const float* __restrict__ aux1, const float* __restrict__ aux2,
     const float* __restrict__ bias,
     float cd, float c1, float c2, int M)
{
    extern __shared__ __align__(16) char smem[];
    bf16* sbuf = (bf16*)smem;

    const int tid  = threadIdx.x;
    const int w    = tid >> 5, lane = tid & 31;
    const int wm   = w >> 2,  wn   = w & 3;        // 2 x 4 warps
    const int m0   = blockIdx.y * 64, n0 = blockIdx.x * 128;
    const size_t ab = (size_t)blockIdx.z * (size_t)M * D;
    const size_t bb = (size_t)blockIdx.z * (size_t)DD;

    const bf16* Al[3] = {A0, A1, A2};
    const bf16* Bl[3] = {B0, B1, B2};
    const int pAi6[6] = {0,0,1,0,1,2}, pBi6[6] = {0,1,0,2,1,0};
    const int pAi3[3] = {0,0,1},       pBi3[3] = {0,1,0};

    float c[2][4][4];
#pragma unroll
    for (int i = 0; i < 2; i++)
#pragma unroll
        for (int j = 0; j < 4; j++)
#pragma unroll
            for (int k = 0; k < 4; k++) c[i][j][k] = 0.0f;

    auto load = [&](int kt) {
        const int stg  = kt & 3;
        const int pass = kt >> 5;
        const int k0   = (kt & 31) << 5;
        const bf16* pA = Al[NP == 6 ? pAi6[pass] : pAi3[pass]] + ab;
        const bf16* pB = Bl[NP == 6 ? pBi6[pass] : pBi3[pass]] + bb;
        bf16* dA0 = sbuf + stg * STAGEE;
        bf16* dB0 = dA0 + STAGEA;
        {   // A: 64 rows x 32 k
            int r = tid >> 2, cb = tid & 3;
            u32 dA = (u32)__cvta_generic_to_shared(dA0 + r * SPITCH + cb * 8);
            asm volatile("cp.async.cg.shared.global [%0], [%1], 16;"
                         :: "r"(dA), "l"(pA + (size_t)(m0 + r) * D + k0 + cb * 8));
        }
#pragma unroll
        for (int i = 0; i < 2; i++) {   // B: 128 rows
            int id = i * 256 + tid;
            int r = id >> 2, cb = id & 3;
            u32 dB = (u32)__cvta_generic_to_shared(dB0 + r * SPITCH + cb * 8);
            asm volatile("cp.async.cg.shared.global [%0], [%1], 16;"
                         :: "r"(dB), "l"(pB + (size_t)(n0 + r) * D + k0 + cb * 8));
        }
        asm volatile("cp.async.commit_group;");
    };

    // hoisted ldmatrix byte offsets (within a stage)
    const int lmRow = lane & 15;
    const int lmCol = (lane >> 4) * 8;
    const u32 sbase = (u32)__cvta_generic_to_shared(sbuf);
    u32 offA[2], offB[2];
#pragma unroll
    for (int mi = 0; mi < 2; mi++)
        offA[mi] = ((wm * 32 + mi * 16 + lmRow) * SPITCH + lmCol) * 2;
#pragma unroll
    for (int nb = 0; nb < 2; nb++)
        offB[nb] = ((wn * 32 + nb * 16 + lmRow) * SPITCH + lmCol) * 2 + STAGEA * 2;

    const int NT = NP * 32;
    load(0); load(1); load(2);
    for (int kt = 0; kt < NT; kt++) {
        const int rem = NT - 1 - kt;
        if (rem >= 2)      asm volatile("cp.async.wait_group 2;");
        else if (rem == 1) asm volatile("cp.async.wait_group 1;");
        else               asm volatile("cp.async.wait_group 0;");
        __syncthreads();
        if (kt + 3 < NT) load(kt + 3);

        const u32 stgb = sbase + (u32)(kt & 3) * (STAGEE * 2);
#pragma unroll
        for (int ks = 0; ks < 2; ks++) {
            const u32 ko = ks * 32;           // 16 bf16 = 32 bytes
            u32 a[2][4], b[4][2];
#pragma unroll
            for (int mi = 0; mi < 2; mi++)
                asm volatile("ldmatrix.sync.aligned.m8n8.x4.shared.b16 {%0,%1,%2,%3}, [%4];"
                    : "=r"(a[mi][0]), "=r"(a[mi][1]), "=r"(a[mi][2]), "=r"(a[mi][3])
                    : "r"(stgb + offA[mi] + ko));
#pragma unroll
            for (int nb = 0; nb < 2; nb++) {
                u32 b0, b1, b2, b3;
                asm volatile("ldmatrix.sync.aligned.m8n8.x4.shared.b16 {%0,%1,%2,%3}, [%4];"
                    : "=r"(b0), "=r"(b1), "=r"(b2), "=r"(b3)
                    : "r"(stgb + offB[nb] + ko));
                b[2 * nb][0]     = b0; b[2 * nb][1]     = b2;
                b[2 * nb + 1][0] = b1; b[2 * nb + 1][1] = b3;
            }
#pragma unroll
            for (int mi = 0; mi < 2; mi++)
#pragma unroll
                for (int ni = 0; ni < 4; ni++)
                    asm volatile(
                        "mma.sync.aligned.m16n8k16.row.col.f32.bf16.bf16.f32 "
                        "{%0,%1,%2,%3}, {%4,%5,%6,%7}, {%8,%9}, {%0,%1,%2,%3};"
                        : "+f"(c[mi][ni][0]), "+f"(c[mi][ni][1]),
                          "+f"(c[mi][ni][2]), "+f"(c[mi][ni][3])
                        : "r"(a[mi][0]), "r"(a[mi][1]), "r"(a[mi][2]), "r"(a[mi][3]),
                          "r"(b[ni][0]), "r"(b[ni][1]));
        }
    }

    // ---------------- fused epilogue ------------------------------------------
    const int lr = lane >> 2, lc = (lane & 3) * 2;
    const int r0 = m0 + wm * 32, cb0 = n0 + wn * 32;
#pragma unroll
    for (int mi = 0; mi < 2; mi++)
#pragma unroll
        for (int ni = 0; ni < 4; ni++)
#pragma unroll
            for (int h = 0; h < 2; h++) {
                const int row = r0 + mi * 16 + lr + h * 8;
                const int col = cb0 + ni * 8 + lc;
                float v0 = c[mi][ni][h * 2], v1 = c[mi][ni][h * 2 + 1];
                const size_t off = ab + (size_t)row * D + col;
                if (EPI == 0) {
                    v0 = c1 * v0; v1 = c1 * v1;
                    if (row == col)     v0 += cd;
                    if (row == col + 1) v1 += cd;
                } else if (EPI == 1) {
                    float2 a1 = *(const float2*)(aux1 + off);
                    v0 = c1 * v0 + c2 * a1.x; v1 = c1 * v1 + c2 * a1.y;
                    if (row == col)     v0 += cd;
                    if (row == col + 1) v1 += cd;
                } else if (EPI == 2) {
                    float2 a1 = *(const float2*)(aux1 + off);
                    float2 a2 = *(const float2*)(aux2 + off);
                    v0 = 0.5f * a1.x + 0.45f * a2.x - 0.5f * v0;
                    v1 = 0.5f * a1.y + 0.45f * a2.y - 0.5f * v1;
                } else if (EPI == 3) {
                    v0 += __ldg(bias + col); v1 += __ldg(bias + col + 1);
                } else { // lipswish
                    v0 += __ldg(bias + col); v1 += __ldg(bias + col + 1);
                    v0 = __fdividef(v0 * (1.0f / 1.1f), 1.0f + __expf(-v0));
                    v1 = __fdividef(v1 * (1.0f / 1.1f), 1.0f + __expf(-v1));
                }
                if (WF) {
                    float2 o; o.x = v0; o.y = v1;
                    *(float2*)(Cf + off) = o;
                }
                if (NW == 2) {
                    unsigned short h0, l0, h1, l1;
                    split2(v0, h0, l0); split2(v1, h1, l1);
                    *(u32*)(C0 + off) = (u32)h0 | ((u32)h1 << 16);
                    *(u32*)(C1 + off) = (u32)l0 | ((u32)l1 << 16);
                } else if (NW == 3) {
                    unsigned short h0, m0s, l0, h1, m1s, l1;
                    split3(v0, h0, m0s, l0); split3(v1, h1, m1s, l1);
                    *(u32*)(C0 + off) = (u32)h0  | ((u32)h1  << 16);
                    *(u32*)(C1 + off) = (u32)m0s | ((u32)m1s << 16);
                    *(u32*)(C2 + off) = (u32)l0  | ((u32)l1  << 16);
                }
                c[mi][ni][h * 2] = v0; c[mi][ni][h * 2 + 1] = v1;
            }

    if (TW) {
        // stage the tile transposed in smem (fp32): ts[col(128)][row(64)]
        float* ts = (float*)smem;
        __syncthreads();
#pragma unroll
        for (int mi = 0; mi < 2; mi++)
#pragma unroll
            for (int ni = 0; ni < 4; ni++)
#pragma unroll
                for (int h = 0; h < 2; h++) {
                    const int rl = wm * 32 + mi * 16 + lr + h * 8;
                    const int cl = wn * 32 + ni * 8 + lc;
                    ts[(cl    ) * TPITCH + rl] = c[mi][ni][h * 2];
                    ts[(cl + 1) * TPITCH + rl] = c[mi][ni][h * 2 + 1];
                }
        __syncthreads();
#pragma unroll
        for (int i = 0; i < 16; i++) {
            const int tr = w * 16 + i;               // output T-row (= col index)
            float2 vv = *(const float2*)&ts[tr * TPITCH + lane * 2];
            const size_t toff = bb + (size_t)(n0 + tr) * D + m0 + lane * 2;
            if (TW == 3) {
                unsigned short h0,m0s,l0, h1,m1s,l1;
                split3(vv.x, h0, m0s, l0); split3(vv.y, h1, m1s, l1);
                *(u32*)(T0 + toff) = (u32)h0  | ((u32)h1  << 16);
                *(u32*)(T1 + toff) = (u32)m0s | ((u32)m1s << 16);
                *(u32*)(T2 + toff) = (u32)l0  | ((u32)l1  << 16);
            } else {
                unsigned short h0,l0, h1,l1;
                split2(vv.x, h0, l0); split2(vv.y, h1, l1);
                *(u32*)(T0 + toff) = (u32)h0 | ((u32)h1 << 16);
                *(u32*)(T1 + toff) = (u32)l0 | ((u32)l1 << 16);
            }
        }
    }
}

// ---------------- pack kernels -------------------------------------------------
__global__ void packS3(const float* __restrict__ in, bf16* __restrict__ o0,
                       bf16* __restrict__ o1, bf16* __restrict__ o2, int n4)
{
    int i = blockIdx.x * 256 + threadIdx.x;
    if (i >= n4) return;
    float4 v = ((const float4*)in)[i];
    ushort4 H, Mv, L;
    split3(v.x, H.x, Mv.x, L.x); split3(v.y, H.y, Mv.y, L.y);
    split3(v.z, H.z, Mv.z, L.z); split3(v.w, H.w, Mv.w, L.w);
    ((ushort4*)o0)[i] = H; ((ushort4*)o1)[i] = Mv; ((ushort4*)o2)[i] = L;
}

__global__ void packS2(const float* __restrict__ in, bf16* __restrict__ o0,
                       bf16* __restrict__ o1, int n4)
{
    int i = blockIdx.x * 256 + threadIdx.x;
    if (i >= n4) return;
    float4 v = ((const float4*)in)[i];
    ushort4 H, L;
    split2(v.x, H.x, L.x); split2(v.y, H.y, L.y);
    split2(v.z, H.z, L.z); split2(v.w, H.w, L.w);
    ((ushort4*)o0)[i] = H; ((ushort4*)o1)[i] = L;
}

__global__ void packC3(const float* __restrict__ w, const float* __restrict__ p,
                       bf16* __restrict__ o0, bf16* __restrict__ o1,
                       bf16* __restrict__ o2, int n4)
{
    int i = blockIdx.x * 256 + threadIdx.x;
    if (i >= n4) return;
    float4 a = ((const float4*)w)[i];
    float4 b = ((const float4*)p)[i];
    float4 v;
    v.x = a.x - 0.9f * b.x; v.y = a.y - 0.9f * b.y;
    v.z = a.z - 0.9f * b.z; v.w = a.w - 0.9f * b.w;
    ushort4 H, Mv, L;
    split3(v.x, H.x, Mv.x, L.x); split3(v.y, H.y, Mv.y, L.y);
    split3(v.z, H.z, Mv.z, L.z); split3(v.w, H.w, Mv.w, L.w);
    ((ushort4*)o0)[i] = H; ((ushort4*)o1)[i] = Mv; ((ushort4*)o2)[i] = L;
}

// transposed 3-way pack (used ONCE, for W)
__global__ void packT3(const float* __restrict__ in, bf16* __restrict__ o0,
                       bf16* __restrict__ o1, bf16* __restrict__ o2)
{
    __shared__ float t[32][33];
    const int b = blockIdx.z;
    in += (size_t)b * DD; o0 += (size_t)b * DD; o1 += (size_t)b * DD; o2 += (size_t)b * DD;
    const int bx = blockIdx.x * 32, by = blockIdx.y * 32;
    const int x = threadIdx.x, y = threadIdx.y;
#pragma unroll
    for (int i = 0; i < 4; i++)
        t[y + i * 8][x] = in[(size_t)(by + y + i * 8) * D + bx + x];
    __syncthreads();
#pragma unroll
    for (int i = 0; i < 4; i++) {
        float v = t[x][y + i * 8];
        unsigned short h, m, l;
        split3(v, h, m, l);
        size_t o = (size_t)(bx + y + i * 8) * D + by + x;
        o0[o] = __ushort_as_bfloat16(h);
        o1[o] = __ushort_as_bfloat16(m);
        o2[o] = __ushort_as_bfloat16(l);
    }
}

// ---------------- launcher ------------------------------------------------------
extern "C" void kernel_launch(void* const* d_in, const int* in_sizes, int n_in,
                              void* d_out, int out_size)
{
    const float* x       = (const float*)d_in[0];
    const float* w[3]    = {(const float*)d_in[1], (const float*)d_in[3], (const float*)d_in[5]};
    const float* bias[3] = {(const float*)d_in[2], (const float*)d_in[4], (const float*)d_in[6]};

    float *Wf, *Yf, *Pf;
    cudaGetSymbolAddress((void**)&Wf, gWf);
    cudaGetSymbolAddress((void**)&Yf, gYf);
    cudaGetSymbolAddress((void**)&Pf, gPf);

    bf16 *WT[3], *Wp[3], *XT[3], *Xa[3], *Xb[3];
    bf16 *Yp[3], *YT[3], *ZT[3];
    bf16 *Qa[3], *Qb[3], *QTa[3], *QTb[3], *Mp[3];
    bf16 *KT[2], *xp[2], *A1[2], *A2[2];
    for (int i = 0; i < 3; i++) {
        cudaGetSymbolAddress((void**)&WT[i],  gWT);  WT[i]  += (size_t)i * 3 * DD;
        cudaGetSymbolAddress((void**)&Wp[i],  gWp);  Wp[i]  += (size_t)i * 3 * DD;
        cudaGetSymbolAddress((void**)&XT[i],  gXT);  XT[i]  += (size_t)i * 3 * DD;
        cudaGetSymbolAddress((void**)&Xa[i],  gXa);  Xa[i]  += (size_t)i * 3 * DD;
        cudaGetSymbolAddress((void**)&Xb[i],  gXb);  Xb[i]  += (size_t)i * 3 * DD;
        cudaGetSymbolAddress((void**)&Yp[i],  gYp);  Yp[i]  += (size_t)i * 3 * DD;
        cudaGetSymbolAddress((void**)&YT[i],  gYT);  YT[i]  += (size_t)i * 3 * DD;
        cudaGetSymbolAddress((void**)&ZT[i],  gZT);  ZT[i]  += (size_t)i * 3 * DD;
        cudaGetSymbolAddress((void**)&Qa[i],  gQa);  Qa[i]  += (size_t)i * 3 * DD;
        cudaGetSymbolAddress((void**)&Qb[i],  gQb);  Qb[i]  += (size_t)i * 3 * DD;
        cudaGetSymbolAddress((void**)&QTa[i], gQTa); QTa[i] += (size_t)i * 3 * DD;
        cudaGetSymbolAddress((void**)&QTb[i], gQTb); QTb[i] += (size_t)i * 3 * DD;
        cudaGetSymbolAddress((void**)&Mp[i],  gMp);  Mp[i]  += (size_t)i * 3 * DD;
    }
    for (int i = 0; i < 2; i++) {
        cudaGetSymbolAddress((void**)&KT[i], gKT); KT[i] += (size_t)i * 3 * DD;
        cudaGetSymbolAddress((void**)&xp[i], gx);  xp[i] += (size_t)i * BSZ * D;
        cudaGetSymbolAddress((void**)&A1[i], gA1); A1[i] += (size_t)i * BSZ * D;
        cudaGetSymbolAddress((void**)&A2[i], gA2); A2[i] += (size_t)i * BSZ * D;
    }

    cudaFuncSetAttribute(gemm<0,1,3,3,3>, cudaFuncAttributeMaxDynamicSharedMemorySize, SMEMSZ);
    cudaFuncSetAttribute(gemm<1,0,0,3,3>, cudaFuncAttributeMaxDynamicSharedMemorySize, SMEMSZ);
    cudaFuncSetAttribute(gemm<0,0,3,3,3>, cudaFuncAttributeMaxDynamicSharedMemorySize, SMEMSZ);
    cudaFuncSetAttribute(gemm<0,0,0,3,3>, cudaFuncAttributeMaxDynamicSharedMemorySize, SMEMSZ);
    cudaFuncSetAttribute(gemm<0,0,0,3,6>, cudaFuncAttributeMaxDynamicSharedMemorySize, SMEMSZ);
    cudaFuncSetAttribute(gemm<0,1,3,3,6>, cudaFuncAttributeMaxDynamicSharedMemorySize, SMEMSZ);
    cudaFuncSetAttribute(gemm<0,0,3,3,6>, cudaFuncAttributeMaxDynamicSharedMemorySize, SMEMSZ);
    cudaFuncSetAttribute(gemm<2,0,0,2,3>, cudaFuncAttributeMaxDynamicSharedMemorySize, SMEMSZ);
    cudaFuncSetAttribute(gemm<4,0,2,0,3>, cudaFuncAttributeMaxDynamicSharedMemorySize, SMEMSZ);
    cudaFuncSetAttribute(gemm<3,1,0,0,3>, cudaFuncAttributeMaxDynamicSharedMemorySize, SMEMSZ);

    for (int i = 0; i < 3; i++)
        cudaMemcpyAsync(Wf + (size_t)i * DD, w[i], (size_t)DD * sizeof(float),
                        cudaMemcpyDeviceToDevice);

    const dim3 gw(8, 16, 3), gx_(8, 256, 1), bk(256);
    const dim3 gt(32, 32, 3), bt(32, 8);
    const float q5a = 3.4445f, q5b = -4.7750f, q5c = 2.0315f;
    const float s0 = 1.0f / 2.2f;
    const float* NF = nullptr;
    bf16* NB = nullptr;

    packS2<<<16384, 256>>>(x, xp[0], xp[1], BSZ * D / 4);
    packS3<<<3072, 256>>>(Wf, Wp[0], Wp[1], Wp[2], 3 * DD / 4);
    packT3<<<gt, bt>>>(Wf, WT[0], WT[1], WT[2]);

    // ---- P = msign(W): 3 cheap quintics + 3 cheap NS + 1 full NS ----
    gemm<0,1,3,3,3><<<gw,bk,SMEMSZ>>>(WT[0],WT[1],WT[2], WT[0],WT[1],WT[2], Yf,
        Yp[0],Yp[1],Yp[2], YT[0],YT[1],YT[2], NF,NF,NF, 0.f, s0*s0, 0.f, D);
    gemm<1,0,0,3,3><<<gw,bk,SMEMSZ>>>(Yp[0],Yp[1],Yp[2], YT[0],YT[1],YT[2], nullptr,
        NB,NB,NB, ZT[0],ZT[1],ZT[2], Yf,NF,NF, q5a, q5c, q5b, D);
    gemm<0,0,3,3,3><<<gw,bk,SMEMSZ>>>(Wp[0],Wp[1],Wp[2], ZT[0],ZT[1],ZT[2], nullptr,
        Xa[0],Xa[1],Xa[2], XT[0],XT[1],XT[2], NF,NF,NF, 0.f, s0, 0.f, D);

    bf16 **cur = Xa, **nxt = Xb;
    for (int it = 0; it < 2; it++) {   // 2 more cheap quintics (3 total)
        gemm<0,1,3,3,3><<<gw,bk,SMEMSZ>>>(XT[0],XT[1],XT[2], XT[0],XT[1],XT[2], Yf,
            Yp[0],Yp[1],Yp[2], YT[0],YT[1],YT[2], NF,NF,NF, 0.f, 1.f, 0.f, D);
        gemm<1,0,0,3,3><<<gw,bk,SMEMSZ>>>(Yp[0],Yp[1],Yp[2], YT[0],YT[1],YT[2], nullptr,
            NB,NB,NB, ZT[0],ZT[1],ZT[2], Yf,NF,NF, q5a, q5c, q5b, D);
        gemm<0,0,3,3,3><<<gw,bk,SMEMSZ>>>(cur[0],cur[1],cur[2], ZT[0],ZT[1],ZT[2], nullptr,
            nxt[0],nxt[1],nxt[2], XT[0],XT[1],XT[2], NF,NF,NF, 0.f, 1.f, 0.f, D);
        bf16** t = cur; cur = nxt; nxt = t;
    }
    for (int it = 0; it < 3; it++) {   // 3 cheap NS
        gemm<0,0,0,3,3><<<gw,bk,SMEMSZ>>>(XT[0],XT[1],XT[2], XT[0],XT[1],XT[2], nullptr,
            NB,NB,NB, ZT[0],ZT[1],ZT[2], NF,NF,NF, 1.5f, -0.5f, 0.f, D);
        gemm<0,0,3,3,3><<<gw,bk,SMEMSZ>>>(cur[0],cur[1],cur[2], ZT[0],ZT[1],ZT[2], nullptr,
            nxt[0],nxt[1],nxt[2], XT[0],XT[1],XT[2], NF,NF,NF, 0.f, 1.f, 0.f, D);
        bf16** t = cur; cur = nxt; nxt = t;
    }
    {   // final NS — FULL precision (sets terminal accuracy of P)
        gemm<0,0,0,3,6><<<gw,bk,SMEMSZ>>>(XT[0],XT[1],XT[2], XT[0],XT[1],XT[2], nullptr,
            NB,NB,NB, ZT[0],ZT[1],ZT[2], NF,NF,NF, 1.5f, -0.5f, 0.f, D);
        gemm<0,1,3,3,6><<<gw,bk,SMEMSZ>>>(cur[0],cur[1],cur[2], ZT[0],ZT[1],ZT[2], Pf,
            nxt[0],nxt[1],nxt[2], XT[0],XT[1],XT[2], NF,NF,NF, 0.f, 1.f, 0.f, D);
        bf16** t = cur; cur = nxt; nxt = t;
    }
    // Pf = P (fp32); XT = packT(P)

    // ---- Q = sign((P^T W - 0.9I)/1.15): 4 cheap quintics + 3 cheap NS + 1 full NS ----
    bf16 **q = Qa, **qT = QTa, **r = Qb, **rT = QTb;
    gemm<0,0,3,3,3><<<gw,bk,SMEMSZ>>>(XT[0],XT[1],XT[2], WT[0],WT[1],WT[2], nullptr,
        q[0],q[1],q[2], qT[0],qT[1],qT[2], NF,NF,NF, -0.9f/1.15f, 1.f/1.15f, 0.f, D);
    for (int it = 0; it < 4; it++) {   // cheap quintics
        gemm<0,1,3,3,3><<<gw,bk,SMEMSZ>>>(q[0],q[1],q[2], qT[0],qT[1],qT[2], Yf,
            Yp[0],Yp[1],Yp[2], YT[0],YT[1],YT[2], NF,NF,NF, 0.f, 1.f, 0.f, D);
        gemm<1,0,0,3,3><<<gw,bk,SMEMSZ>>>(Yp[0],Yp[1],Yp[2], YT[0],YT[1],YT[2], nullptr,
            NB,NB,NB, ZT[0],ZT[1],ZT[2], Yf,NF,NF, q5a, q5c, q5b, D);
        gemm<0,0,3,3,3><<<gw,bk,SMEMSZ>>>(q[0],q[1],q[2], ZT[0],ZT[1],ZT[2], nullptr,
            r[0],r[1],r[2], rT[0],rT[1],rT[2], NF,NF,NF, 0.f, 1.f, 0.f, D);
        bf16** t = q; q = r; r = t;
        t = qT; qT = rT; rT = t;
    }
    for (int it = 0; it < 3; it++) {   // cheap NS
        gemm<0,0,0,3,3><<<gw,bk,SMEMSZ>>>(q[0],q[1],q[2], qT[0],qT[1],qT[2], nullptr,
            NB,NB,NB, ZT[0],ZT[1],ZT[2], NF,NF,NF, 1.5f, -0.5f, 0.f, D);
        gemm<0,0,3,3,3><<<gw,bk,SMEMSZ>>>(q[0],q[1],q[2], ZT[0],ZT[1],ZT[2], nullptr,
            r[0],r[1],r[2], rT[0],rT[1],rT[2], NF,NF,NF, 0.f, 1.f, 0.f, D);
        bf16** t = q; q = r; r = t;
        t = qT; qT = rT; rT = t;
    }
    {   // final NS — FULL precision (sets terminal accuracy of Q)
        gemm<0,0,0,3,6><<<gw,bk,SMEMSZ>>>(q[0],q[1],q[2], qT[0],qT[1],qT[2], nullptr,
            NB,NB,NB, ZT[0],ZT[1],ZT[2], NF,NF,NF, 1.5f, -0.5f, 0.f, D);
        gemm<0,0,3,3,6><<<gw,bk,SMEMSZ>>>(q[0],q[1],q[2], ZT[0],ZT[1],ZT[2], nullptr,
            r[0],r[1],r[2], rT[0],rT[1],rT[2], NF,NF,NF, 0.f, 1.f, 0.f, D);
        bf16** t = q; q = r; r = t;
        t = qT; qT = rT; rT = t;
    }

    // ---- K = 0.5(W + 0.9P - (W-0.9P)Q): KT produced directly (2-way, transposed) ----
    packC3<<<3072, 256>>>(Wf, Pf, Mp[0], Mp[1], Mp[2], 3 * DD / 4);
    gemm<2,0,0,2,3><<<gw,bk,SMEMSZ>>>(Mp[0],Mp[1],Mp[2], qT[0],qT[1],qT[2], nullptr,
        NB,NB,NB, KT[0],KT[1],NB, Wf, Pf, NF, 0.f, 0.f, 0.f, D);

    // ---- activation chain (3-pass 2-way; terminal) ----
    gemm<4,0,2,0,3><<<gx_,bk,SMEMSZ>>>(xp[0],xp[1],NB, KT[0],KT[1],NB, nullptr,
        A1[0],A1[1],NB, NB,NB,NB, NF,NF, bias[0], 0.f,0.f,0.f, BSZ);
    gemm<4,0,2,0,3><<<gx_,bk,SMEMSZ>>>(A1[0],A1[1],NB, KT[0]+DD,KT[1]+DD,NB, nullptr,
        A2[0],A2[1],NB, NB,NB,NB, NF,NF, bias[1], 0.f,0.f,0.f, BSZ);
    gemm<3,1,0,0,3><<<gx_,bk,SMEMSZ>>>(A2[0],A2[1],NB, KT[0]+2*DD,KT[1]+2*DD,NB, (float*)d_out,
        NB,NB,NB, NB,NB,NB, NF,NF, bias[2], 0.f,0.f,0.f, BSZ);
}